// round 11
// baseline (speedup 1.0000x reference)
#include <cuda_runtime.h>
#include <cuda_fp16.h>
#include <cstdint>

#define B_ 2
#define T_ 2048
#define HID_ 2048
#define NH_ 16
#define KVH_ 4
#define HD_ 128
#define NQKV 3072
#define KDIM 2048

// fp16 QKV GEMM output (Q | K | V per token row)
__device__ __half g_qkv[(size_t)B_ * T_ * NQKV];
// fp16 GEMM operands
__device__ __half g_hid_h[(size_t)4096 * KDIM];
__device__ __half g_wqkv_h[(size_t)KDIM * NQKV];
__device__ __half g_wo_h[(size_t)KDIM * HID_];
__device__ __half g_ctx_h[(size_t)4096 * HID_];   // written by flash epilogue
// fp16 roped flash inputs
__device__ __half g_qf[(size_t)B_ * T_ * NH_ * HD_];
__device__ __half g_kf[(size_t)B_ * T_ * KVH_ * HD_];

// ---------------------------------------------------------------------------
// helpers
// ---------------------------------------------------------------------------
__device__ __forceinline__ void cp16(uint32_t s, const void* g) {
    asm volatile("cp.async.cg.shared.global [%0], [%1], 16;\n" :: "r"(s), "l"(g));
}
__device__ __forceinline__ void cp_commit() {
    asm volatile("cp.async.commit_group;\n" ::);
}
__device__ __forceinline__ void mma_f16(float* c, const uint32_t* a, const uint32_t* b) {
    asm volatile(
        "mma.sync.aligned.m16n8k16.row.col.f32.f16.f16.f32 "
        "{%0,%1,%2,%3}, {%4,%5,%6,%7}, {%8,%9}, {%0,%1,%2,%3};\n"
        : "+f"(c[0]), "+f"(c[1]), "+f"(c[2]), "+f"(c[3])
        : "r"(a[0]), "r"(a[1]), "r"(a[2]), "r"(a[3]), "r"(b[0]), "r"(b[1]));
}
__device__ __forceinline__ void ldsm4(uint32_t* d, uint32_t addr) {
    asm volatile("ldmatrix.sync.aligned.m8n8.x4.shared.b16 {%0,%1,%2,%3}, [%4];\n"
                 : "=r"(d[0]), "=r"(d[1]), "=r"(d[2]), "=r"(d[3]) : "r"(addr));
}
__device__ __forceinline__ void ldsm4t(uint32_t* d, uint32_t addr) {
    asm volatile("ldmatrix.sync.aligned.m8n8.x4.trans.shared.b16 {%0,%1,%2,%3}, [%4];\n"
                 : "=r"(d[0]), "=r"(d[1]), "=r"(d[2]), "=r"(d[3]) : "r"(addr));
}
__device__ __forceinline__ float ex2(float x) {
    float r;
    asm("ex2.approx.f32 %0, %1;" : "=f"(r) : "f"(x));
    return r;
}
__device__ __forceinline__ uint32_t packh2(float a, float b) {
    __half2 t = __floats2half2_rn(a, b);
    return *(uint32_t*)&t;
}

// ---------------------------------------------------------------------------
// converts
// ---------------------------------------------------------------------------
__global__ void cvt_f16(const float* __restrict__ in, __half* __restrict__ out,
                        int total8) {
    int i = blockIdx.x * blockDim.x + threadIdx.x;
    if (i >= total8) return;
    float4 x0 = *(const float4*)(in + (size_t)i * 8);
    float4 x1 = *(const float4*)(in + (size_t)i * 8 + 4);
    __half2 h[4];
    h[0] = __floats2half2_rn(x0.x, x0.y);
    h[1] = __floats2half2_rn(x0.z, x0.w);
    h[2] = __floats2half2_rn(x1.x, x1.y);
    h[3] = __floats2half2_rn(x1.z, x1.w);
    *(uint4*)(out + (size_t)i * 8) = *(uint4*)h;
}

// all 4 weight matrices in one launch
#define WQ_E (KDIM * 2048)
#define WK_E (KDIM * 512)
#define WV_E (KDIM * 512)
#define WO_E (KDIM * 2048)
__global__ void cvt_weights(const float* __restrict__ Wq, const float* __restrict__ Wk,
                            const float* __restrict__ Wv, const float* __restrict__ Wo,
                            __half* __restrict__ wqkv, __half* __restrict__ wo) {
    int i = blockIdx.x * blockDim.x + threadIdx.x;
    if (i < WQ_E) {
        int k = i >> 11, n = i & 2047;
        wqkv[(size_t)k * NQKV + n] = __float2half(Wq[i]);
        return;
    }
    i -= WQ_E;
    if (i < WK_E) {
        int k = i >> 9, n = i & 511;
        wqkv[(size_t)k * NQKV + 2048 + n] = __float2half(Wk[i]);
        return;
    }
    i -= WK_E;
    if (i < WV_E) {
        int k = i >> 9, n = i & 511;
        wqkv[(size_t)k * NQKV + 2560 + n] = __float2half(Wv[i]);
        return;
    }
    i -= WV_E;
    if (i < WO_E) {
        int k = i >> 11, n = i & 2047;
        wo[(size_t)k * 2048 + n] = __float2half(Wo[i]);
    }
}

// ---------------------------------------------------------------------------
// fp16 GEMM, templated output type (fp16 for QKV, fp32 for final out)
// ---------------------------------------------------------------------------
#define GBM 128
#define GBN 128
#define GBK 64
#define GSTAGES 3
#define A_STAGE_BYTES (GBM * GBK * 2)
#define B_STAGE_BYTES (GBK * GBN * 2)

template <typename OutT>
__global__ __launch_bounds__(256) void f16gemm(const __half* __restrict__ A,
                                               const __half* __restrict__ B,
                                               OutT* __restrict__ C,
                                               int M, int N, int K) {
    extern __shared__ char sm[];
    const uint32_t smBase = (uint32_t)__cvta_generic_to_shared(sm);
    const uint32_t aBase = smBase;
    const uint32_t bBase = smBase + GSTAGES * A_STAGE_BYTES;

    const int tid = threadIdx.x;
    const int bm = blockIdx.y, bn = blockIdx.x;
    const int warp = tid >> 5, lane = tid & 31;
    const int wm = warp >> 2;
    const int wn = warp & 3;

    float acc[4][4][4];
#pragma unroll
    for (int mi = 0; mi < 4; mi++)
#pragma unroll
        for (int ni = 0; ni < 4; ni++)
#pragma unroll
            for (int e = 0; e < 4; e++) acc[mi][ni][e] = 0.f;

    const int KT = K / GBK;

    auto load_stage = [&](int sidx, int kt) {
#pragma unroll
        for (int i = 0; i < 4; i++) {
            int q = tid + i * 256;
            int r = q >> 3, c = q & 7;
            const __half* g = A + (size_t)(bm * GBM + r) * K + kt * GBK + c * 8;
            uint32_t s = aBase + sidx * A_STAGE_BYTES + r * 128 + (((c ^ (r & 7)) & 7) << 4);
            cp16(s, g);
        }
#pragma unroll
        for (int i = 0; i < 4; i++) {
            int q = tid + i * 256;
            int r = q >> 4, c = q & 15;
            const __half* g = B + (size_t)(kt * GBK + r) * N + bn * GBN + c * 8;
            int ch = (c & 8) | ((c ^ (r & 7)) & 7);
            uint32_t s = bBase + sidx * B_STAGE_BYTES + r * 256 + (ch << 4);
            cp16(s, g);
        }
    };

#pragma unroll
    for (int s = 0; s < GSTAGES - 1; s++) {
        load_stage(s, s);
        cp_commit();
    }
    asm volatile("cp.async.wait_group %0;\n" :: "n"(GSTAGES - 2));
    __syncthreads();

    const int a_row = wm * 64 + (lane & 15);
    const int a_col8 = (lane >> 4) * 8;
    const int b_row = (lane & 15);
    const int b_colb = wn * 32 + (lane >> 4) * 8;

    for (int kt = 0; kt < KT; kt++) {
        const int cur = kt % GSTAGES;
        if (kt + GSTAGES - 1 < KT) load_stage((kt + GSTAGES - 1) % GSTAGES, kt + GSTAGES - 1);
        cp_commit();

        const uint32_t aS = aBase + cur * A_STAGE_BYTES;
        const uint32_t bS = bBase + cur * B_STAGE_BYTES;

#pragma unroll
        for (int ks = 0; ks < GBK / 16; ks++) {
            uint32_t af[4][4];
#pragma unroll
            for (int mi = 0; mi < 4; mi++) {
                int row = a_row + mi * 16;
                int col = ks * 16 + a_col8;
                uint32_t addr = aS + row * 128 + ((((col >> 3) ^ (row & 7)) & 7) << 4);
                ldsm4(af[mi], addr);
            }
            uint32_t bfr[4][2];
#pragma unroll
            for (int np = 0; np < 2; np++) {
                int row = ks * 16 + b_row;
                int col = b_colb + np * 16;
                int ch = (col >> 3);
                ch = (ch & 8) | ((ch ^ (row & 7)) & 7);
                uint32_t addr = bS + row * 256 + (ch << 4);
                uint32_t tmp[4];
                ldsm4t(tmp, addr);
                bfr[np * 2][0] = tmp[0]; bfr[np * 2][1] = tmp[1];
                bfr[np * 2 + 1][0] = tmp[2]; bfr[np * 2 + 1][1] = tmp[3];
            }
#pragma unroll
            for (int mi = 0; mi < 4; mi++)
#pragma unroll
                for (int ni = 0; ni < 4; ni++)
                    mma_f16(acc[mi][ni], af[mi], bfr[ni]);
        }

        asm volatile("cp.async.wait_group %0;\n" :: "n"(GSTAGES - 2));
        __syncthreads();
    }

#pragma unroll
    for (int mi = 0; mi < 4; mi++) {
#pragma unroll
        for (int ni = 0; ni < 4; ni++) {
            int row = bm * GBM + wm * 64 + mi * 16 + (lane >> 2);
            int col = bn * GBN + wn * 32 + ni * 8 + (lane & 3) * 2;
            if constexpr (sizeof(OutT) == 4) {
                float* Cp = (float*)C;
                *(float2*)&Cp[(size_t)row * N + col] = make_float2(acc[mi][ni][0], acc[mi][ni][1]);
                *(float2*)&Cp[(size_t)(row + 8) * N + col] = make_float2(acc[mi][ni][2], acc[mi][ni][3]);
            } else {
                __half* Cp = (__half*)C;
                *(uint32_t*)&Cp[(size_t)row * N + col] = packh2(acc[mi][ni][0], acc[mi][ni][1]);
                *(uint32_t*)&Cp[(size_t)(row + 8) * N + col] = packh2(acc[mi][ni][2], acc[mi][ni][3]);
            }
        }
    }
}

// ---------------------------------------------------------------------------
// Fused RoPE for Q and K (reads fp16 qkv, writes dense fp16 qf/kf)
// ---------------------------------------------------------------------------
#define QP (B_ * T_ * NH_ * 64)    // q rotation pairs
#define KP (B_ * T_ * KVH_ * 64)   // k rotation pairs
__global__ void rope_qk(const __half* __restrict__ qkv,
                        const float* __restrict__ cosp, const float* __restrict__ sinp,
                        __half* __restrict__ qf, __half* __restrict__ kf,
                        float qscale) {
    int idx = blockIdx.x * blockDim.x + threadIdx.x;
    int nheads, hoff;
    __half* o;
    float scale;
    if (idx < QP) {
        nheads = NH_; hoff = 0; o = qf; scale = qscale;
    } else if (idx < QP + KP) {
        idx -= QP;
        nheads = KVH_; hoff = 2048; o = kf; scale = 1.0f;
    } else return;
    int d = idx & 63;
    int h = (idx >> 6) % nheads;
    int tok = idx / (64 * nheads);
    int t = tok & (T_ - 1);
    size_t ib = (size_t)tok * NQKV + hoff + h * HD_;
    size_t ob = ((size_t)tok * nheads + h) * HD_;
    float c1 = cosp[t * HD_ + d], s1 = sinp[t * HD_ + d];
    float c2 = cosp[t * HD_ + d + 64], s2 = sinp[t * HD_ + d + 64];
    float x1 = __half2float(qkv[ib + d]), x2 = __half2float(qkv[ib + d + 64]);
    o[ob + d] = __float2half((x1 * c1 - x2 * s1) * scale);
    o[ob + d + 64] = __float2half((x2 * c2 + x1 * s2) * scale);
}

// ---------------------------------------------------------------------------
// fp16 flash attention. BM=BN=64, 128 threads, 48 KB smem, 4 CTAs/SM.
// V read directly from qkv (stride NQKV, offset 2560). Largest qtile first.
// ---------------------------------------------------------------------------
#define FTILE (64 * 128 * 2)

__global__ __launch_bounds__(128) void flash_f16(const __half* __restrict__ Qf,
                                                 const __half* __restrict__ Kf,
                                                 const __half* __restrict__ qkv,
                                                 __half* __restrict__ ctxH) {
    extern __shared__ char sm[];
    const uint32_t smBase = (uint32_t)__cvta_generic_to_shared(sm);
    const uint32_t sQ = smBase;
    const uint32_t sK = smBase + FTILE;
    const uint32_t sV = smBase + 2 * FTILE;

    const int tid = threadIdx.x;
    const int warp = tid >> 5, lane = tid & 31;
    const int qtile = (T_ / 64 - 1) - blockIdx.x;   // largest work first
    const int h = blockIdx.y;
    const int b = blockIdx.z;
    const int kvh = h / (NH_ / KVH_);
    const int q0 = qtile * 64;

    auto loadTile = [&](uint32_t sbase, const __half* g, size_t gbase, int gstride) {
#pragma unroll
        for (int i = 0; i < 8; i++) {
            int q = tid + i * 128;
            int r = q >> 4, c = q & 15;
            int ch = (c & 8) | ((c ^ (r & 7)) & 7);
            cp16(sbase + r * 256 + (ch << 4), g + gbase + (size_t)r * gstride + c * 8);
        }
    };

    const size_t qgb = ((size_t)(b * T_ + q0) * NH_ + h) * HD_;
    loadTile(sQ, Qf, qgb, NH_ * HD_);
    cp_commit();

    float oAcc[16][4];
#pragma unroll
    for (int j = 0; j < 16; j++)
#pragma unroll
        for (int e = 0; e < 4; e++) oAcc[j][e] = 0.f;
    float mrow[2] = {-1e30f, -1e30f};
    float lrow[2] = {0.f, 0.f};

    for (int t0 = 0; t0 <= qtile; t0++) {
        const int s0 = t0 * 64;
        __syncthreads();
        const size_t kgb = ((size_t)(b * T_ + s0) * KVH_ + kvh) * HD_;
        const size_t vgb = (size_t)(b * T_ + s0) * NQKV + 2560 + kvh * HD_;
        loadTile(sK, Kf, kgb, KVH_ * HD_);
        loadTile(sV, qkv, vgb, NQKV);
        cp_commit();
        asm volatile("cp.async.wait_group 0;\n" ::);
        __syncthreads();

        // ---- S = Q K^T ----
        float sAcc[8][4];
#pragma unroll
        for (int j = 0; j < 8; j++)
#pragma unroll
            for (int e = 0; e < 4; e++) sAcc[j][e] = 0.f;

#pragma unroll
        for (int ks = 0; ks < 8; ks++) {
            int arow = warp * 16 + (lane & 15);
            int ac = ks * 2 + (lane >> 4);
            int ach = (ac & 8) | ((ac ^ (arow & 7)) & 7);
            uint32_t a4[4];
            ldsm4(a4, sQ + arow * 256 + (ach << 4));
            int krow_base = (lane & 7) + ((lane >> 4) & 1) * 8;
            int kc = ks * 2 + ((lane >> 3) & 1);
#pragma unroll
            for (int jp = 0; jp < 4; jp++) {
                int krow = jp * 16 + krow_base;
                int kch = (kc & 8) | ((kc ^ (krow & 7)) & 7);
                uint32_t b4[4];
                ldsm4(b4, sK + krow * 256 + (kch << 4));
                mma_f16(sAcc[jp * 2], a4, b4);
                mma_f16(sAcc[jp * 2 + 1], a4, &b4[2]);
            }
        }

        if (t0 == qtile) {
            int r0 = warp * 16 + (lane >> 2);
#pragma unroll
            for (int j = 0; j < 8; j++) {
                int cb = j * 8 + (lane & 3) * 2;
                if (cb > r0) sAcc[j][0] = -1e30f;
                if (cb + 1 > r0) sAcc[j][1] = -1e30f;
                if (cb > r0 + 8) sAcc[j][2] = -1e30f;
                if (cb + 1 > r0 + 8) sAcc[j][3] = -1e30f;
            }
        }

        // ---- online softmax ----
        float mx0 = -1e30f, mx1 = -1e30f;
#pragma unroll
        for (int j = 0; j < 8; j++) {
            mx0 = fmaxf(mx0, fmaxf(sAcc[j][0], sAcc[j][1]));
            mx1 = fmaxf(mx1, fmaxf(sAcc[j][2], sAcc[j][3]));
        }
        mx0 = fmaxf(mx0, __shfl_xor_sync(0xffffffffu, mx0, 1));
        mx0 = fmaxf(mx0, __shfl_xor_sync(0xffffffffu, mx0, 2));
        mx1 = fmaxf(mx1, __shfl_xor_sync(0xffffffffu, mx1, 1));
        mx1 = fmaxf(mx1, __shfl_xor_sync(0xffffffffu, mx1, 2));
        float mn0 = fmaxf(mrow[0], mx0);
        float mn1 = fmaxf(mrow[1], mx1);
        float al0 = ex2(mrow[0] - mn0);
        float al1 = ex2(mrow[1] - mn1);
        mrow[0] = mn0;
        mrow[1] = mn1;
        float sum0 = 0.f, sum1 = 0.f;
#pragma unroll
        for (int j = 0; j < 8; j++) {
            sAcc[j][0] = ex2(sAcc[j][0] - mn0);
            sAcc[j][1] = ex2(sAcc[j][1] - mn0);
            sAcc[j][2] = ex2(sAcc[j][2] - mn1);
            sAcc[j][3] = ex2(sAcc[j][3] - mn1);
            sum0 += sAcc[j][0] + sAcc[j][1];
            sum1 += sAcc[j][2] + sAcc[j][3];
        }
        sum0 += __shfl_xor_sync(0xffffffffu, sum0, 1);
        sum0 += __shfl_xor_sync(0xffffffffu, sum0, 2);
        sum1 += __shfl_xor_sync(0xffffffffu, sum1, 1);
        sum1 += __shfl_xor_sync(0xffffffffu, sum1, 2);
        lrow[0] = lrow[0] * al0 + sum0;
        lrow[1] = lrow[1] * al1 + sum1;
#pragma unroll
        for (int j = 0; j < 16; j++) {
            oAcc[j][0] *= al0;
            oAcc[j][1] *= al0;
            oAcc[j][2] *= al1;
            oAcc[j][3] *= al1;
        }

        // ---- O += P V ----
        int vrow_b = (lane & 15);
        int vcb = (lane >> 4);
#pragma unroll
        for (int kt = 0; kt < 4; kt++) {
            uint32_t pf[4];
            pf[0] = packh2(sAcc[2 * kt][0], sAcc[2 * kt][1]);
            pf[1] = packh2(sAcc[2 * kt][2], sAcc[2 * kt][3]);
            pf[2] = packh2(sAcc[2 * kt + 1][0], sAcc[2 * kt + 1][1]);
            pf[3] = packh2(sAcc[2 * kt + 1][2], sAcc[2 * kt + 1][3]);
            int vrow = kt * 16 + vrow_b;
#pragma unroll
            for (int jp2 = 0; jp2 < 8; jp2++) {
                int vc = jp2 * 2 + vcb;
                int vch = (vc & 8) | ((vc ^ (vrow & 7)) & 7);
                uint32_t v4[4];
                ldsm4t(v4, sV + vrow * 256 + (vch << 4));
                mma_f16(oAcc[jp2 * 2], pf, v4);
                mma_f16(oAcc[jp2 * 2 + 1], pf, &v4[2]);
            }
        }
    }

    // epilogue: normalize, write fp16 ctx (b,t,h,d)
    float inv0 = 1.f / lrow[0];
    float inv1 = 1.f / lrow[1];
    int r0 = q0 + warp * 16 + (lane >> 2);
    size_t row0 = (size_t)(b * T_ + r0) * HID_;
    size_t row1 = row0 + (size_t)8 * HID_;
#pragma unroll
    for (int j = 0; j < 16; j++) {
        int col = h * HD_ + j * 8 + (lane & 3) * 2;
        *(uint32_t*)(ctxH + row0 + col) = packh2(oAcc[j][0] * inv0, oAcc[j][1] * inv0);
        *(uint32_t*)(ctxH + row1 + col) = packh2(oAcc[j][2] * inv1, oAcc[j][3] * inv1);
    }
}

// ---------------------------------------------------------------------------
// Launch
// ---------------------------------------------------------------------------
extern "C" void kernel_launch(void* const* d_in, const int* in_sizes, int n_in,
                              void* d_out, int out_size) {
    const float* hidden = (const float*)d_in[0];
    const float* cosp = (const float*)d_in[2];
    const float* sinp = (const float*)d_in[3];
    const float* Wq = (const float*)d_in[4];
    const float* Wk = (const float*)d_in[5];
    const float* Wv = (const float*)d_in[6];
    const float* Wo = (const float*)d_in[7];
    float* out = (float*)d_out;

    __half *qkv, *hid_h, *wqkv_h, *wo_h, *ctx_h, *qf, *kf;
    cudaGetSymbolAddress((void**)&qkv, g_qkv);
    cudaGetSymbolAddress((void**)&hid_h, g_hid_h);
    cudaGetSymbolAddress((void**)&wqkv_h, g_wqkv_h);
    cudaGetSymbolAddress((void**)&wo_h, g_wo_h);
    cudaGetSymbolAddress((void**)&ctx_h, g_ctx_h);
    cudaGetSymbolAddress((void**)&qf, g_qf);
    cudaGetSymbolAddress((void**)&kf, g_kf);

    const int M = B_ * T_;  // 4096

    constexpr int GEMM_SMEM = GSTAGES * (A_STAGE_BYTES + B_STAGE_BYTES);  // 96 KB
    cudaFuncSetAttribute(f16gemm<__half>, cudaFuncAttributeMaxDynamicSharedMemorySize, GEMM_SMEM);
    cudaFuncSetAttribute(f16gemm<float>, cudaFuncAttributeMaxDynamicSharedMemorySize, GEMM_SMEM);
    cudaFuncSetAttribute(flash_f16, cudaFuncAttributeMaxDynamicSharedMemorySize, 3 * FTILE);

    // converts (2 launches)
    cvt_f16<<<(M * KDIM / 8 + 255) / 256, 256>>>(hidden, hid_h, M * KDIM / 8);
    cvt_weights<<<(WQ_E + WK_E + WV_E + WO_E + 255) / 256, 256>>>(Wq, Wk, Wv, Wo, wqkv_h, wo_h);

    // fused QKV projection -> fp16
    f16gemm<__half><<<dim3(NQKV / GBN, M / GBM), 256, GEMM_SMEM>>>(hid_h, wqkv_h, qkv, M, NQKV, KDIM);

    // fused RoPE for Q and K
    const float qscale = 1.4426950408889634f * 0.08838834764831845f;
    rope_qk<<<(QP + KP + 255) / 256, 256>>>(qkv, cosp, sinp, qf, kf, qscale);

    // flash attention (V direct from qkv) -> fp16 ctx
    flash_f16<<<dim3(T_ / 64, NH_, B_), 128, 3 * FTILE>>>(qf, kf, qkv, ctx_h);

    // output projection -> fp32
    f16gemm<float><<<dim3(2048 / GBN, M / GBM), 256, GEMM_SMEM>>>(ctx_h, wo_h, out, M, 2048, KDIM);
}

// round 12
// speedup vs baseline: 1.0477x; 1.0477x over previous
#include <cuda_runtime.h>
#include <cuda_fp16.h>
#include <cstdint>

#define B_ 2
#define T_ 2048
#define HID_ 2048
#define NH_ 16
#define KVH_ 4
#define HD_ 128
#define NQKV 3072
#define KDIM 2048

// fp16 QKV GEMM output (Q | K | V per token row)
__device__ __half g_qkv[(size_t)B_ * T_ * NQKV];
// fp16 GEMM operands
__device__ __half g_hid_h[(size_t)4096 * KDIM];
__device__ __half g_wqkv_h[(size_t)KDIM * NQKV];
__device__ __half g_wo_h[(size_t)KDIM * HID_];
__device__ __half g_ctx_h[(size_t)4096 * HID_];   // written by flash epilogue
// fp16 flash inputs (dense)
__device__ __half g_qf[(size_t)B_ * T_ * NH_ * HD_];
__device__ __half g_kf[(size_t)B_ * T_ * KVH_ * HD_];
__device__ __half g_vf[(size_t)B_ * T_ * KVH_ * HD_];

// ---------------------------------------------------------------------------
// helpers
// ---------------------------------------------------------------------------
__device__ __forceinline__ void cp16(uint32_t s, const void* g) {
    asm volatile("cp.async.cg.shared.global [%0], [%1], 16;\n" :: "r"(s), "l"(g));
}
__device__ __forceinline__ void cp_commit() {
    asm volatile("cp.async.commit_group;\n" ::);
}
__device__ __forceinline__ void mma_f16(float* c, const uint32_t* a, const uint32_t* b) {
    asm volatile(
        "mma.sync.aligned.m16n8k16.row.col.f32.f16.f16.f32 "
        "{%0,%1,%2,%3}, {%4,%5,%6,%7}, {%8,%9}, {%0,%1,%2,%3};\n"
        : "+f"(c[0]), "+f"(c[1]), "+f"(c[2]), "+f"(c[3])
        : "r"(a[0]), "r"(a[1]), "r"(a[2]), "r"(a[3]), "r"(b[0]), "r"(b[1]));
}
__device__ __forceinline__ void ldsm4(uint32_t* d, uint32_t addr) {
    asm volatile("ldmatrix.sync.aligned.m8n8.x4.shared.b16 {%0,%1,%2,%3}, [%4];\n"
                 : "=r"(d[0]), "=r"(d[1]), "=r"(d[2]), "=r"(d[3]) : "r"(addr));
}
__device__ __forceinline__ void ldsm4t(uint32_t* d, uint32_t addr) {
    asm volatile("ldmatrix.sync.aligned.m8n8.x4.trans.shared.b16 {%0,%1,%2,%3}, [%4];\n"
                 : "=r"(d[0]), "=r"(d[1]), "=r"(d[2]), "=r"(d[3]) : "r"(addr));
}
__device__ __forceinline__ float ex2(float x) {
    float r;
    asm("ex2.approx.f32 %0, %1;" : "=f"(r) : "f"(x));
    return r;
}
__device__ __forceinline__ uint32_t packh2(float a, float b) {
    __half2 t = __floats2half2_rn(a, b);
    return *(uint32_t*)&t;
}

// ---------------------------------------------------------------------------
// converts
// ---------------------------------------------------------------------------
__global__ void cvt_f16(const float* __restrict__ in, __half* __restrict__ out,
                        int total8) {
    int i = blockIdx.x * blockDim.x + threadIdx.x;
    if (i >= total8) return;
    float4 x0 = *(const float4*)(in + (size_t)i * 8);
    float4 x1 = *(const float4*)(in + (size_t)i * 8 + 4);
    __half2 h[4];
    h[0] = __floats2half2_rn(x0.x, x0.y);
    h[1] = __floats2half2_rn(x0.z, x0.w);
    h[2] = __floats2half2_rn(x1.x, x1.y);
    h[3] = __floats2half2_rn(x1.z, x1.w);
    *(uint4*)(out + (size_t)i * 8) = *(uint4*)h;
}

// all 4 weight matrices in one launch
#define WQ_E (KDIM * 2048)
#define WK_E (KDIM * 512)
#define WV_E (KDIM * 512)
#define WO_E (KDIM * 2048)
__global__ void cvt_weights(const float* __restrict__ Wq, const float* __restrict__ Wk,
                            const float* __restrict__ Wv, const float* __restrict__ Wo,
                            __half* __restrict__ wqkv, __half* __restrict__ wo) {
    int i = blockIdx.x * blockDim.x + threadIdx.x;
    if (i < WQ_E) {
        int k = i >> 11, n = i & 2047;
        wqkv[(size_t)k * NQKV + n] = __float2half(Wq[i]);
        return;
    }
    i -= WQ_E;
    if (i < WK_E) {
        int k = i >> 9, n = i & 511;
        wqkv[(size_t)k * NQKV + 2048 + n] = __float2half(Wk[i]);
        return;
    }
    i -= WK_E;
    if (i < WV_E) {
        int k = i >> 9, n = i & 511;
        wqkv[(size_t)k * NQKV + 2560 + n] = __float2half(Wv[i]);
        return;
    }
    i -= WV_E;
    if (i < WO_E) {
        int k = i >> 11, n = i & 2047;
        wo[(size_t)k * 2048 + n] = __float2half(Wo[i]);
    }
}

// ---------------------------------------------------------------------------
// fp16 GEMM, templated output type (fp16 for QKV, fp32 for final out)
// ---------------------------------------------------------------------------
#define GBM 128
#define GBN 128
#define GBK 64
#define GSTAGES 3
#define A_STAGE_BYTES (GBM * GBK * 2)
#define B_STAGE_BYTES (GBK * GBN * 2)

template <typename OutT>
__global__ __launch_bounds__(256) void f16gemm(const __half* __restrict__ A,
                                               const __half* __restrict__ B,
                                               OutT* __restrict__ C,
                                               int M, int N, int K) {
    extern __shared__ char sm[];
    const uint32_t smBase = (uint32_t)__cvta_generic_to_shared(sm);
    const uint32_t aBase = smBase;
    const uint32_t bBase = smBase + GSTAGES * A_STAGE_BYTES;

    const int tid = threadIdx.x;
    const int bm = blockIdx.y, bn = blockIdx.x;
    const int warp = tid >> 5, lane = tid & 31;
    const int wm = warp >> 2;
    const int wn = warp & 3;

    float acc[4][4][4];
#pragma unroll
    for (int mi = 0; mi < 4; mi++)
#pragma unroll
        for (int ni = 0; ni < 4; ni++)
#pragma unroll
            for (int e = 0; e < 4; e++) acc[mi][ni][e] = 0.f;

    const int KT = K / GBK;

    auto load_stage = [&](int sidx, int kt) {
#pragma unroll
        for (int i = 0; i < 4; i++) {
            int q = tid + i * 256;
            int r = q >> 3, c = q & 7;
            const __half* g = A + (size_t)(bm * GBM + r) * K + kt * GBK + c * 8;
            uint32_t s = aBase + sidx * A_STAGE_BYTES + r * 128 + (((c ^ (r & 7)) & 7) << 4);
            cp16(s, g);
        }
#pragma unroll
        for (int i = 0; i < 4; i++) {
            int q = tid + i * 256;
            int r = q >> 4, c = q & 15;
            const __half* g = B + (size_t)(kt * GBK + r) * N + bn * GBN + c * 8;
            int ch = (c & 8) | ((c ^ (r & 7)) & 7);
            uint32_t s = bBase + sidx * B_STAGE_BYTES + r * 256 + (ch << 4);
            cp16(s, g);
        }
    };

#pragma unroll
    for (int s = 0; s < GSTAGES - 1; s++) {
        load_stage(s, s);
        cp_commit();
    }
    asm volatile("cp.async.wait_group %0;\n" :: "n"(GSTAGES - 2));
    __syncthreads();

    const int a_row = wm * 64 + (lane & 15);
    const int a_col8 = (lane >> 4) * 8;
    const int b_row = (lane & 15);
    const int b_colb = wn * 32 + (lane >> 4) * 8;

    for (int kt = 0; kt < KT; kt++) {
        const int cur = kt % GSTAGES;
        if (kt + GSTAGES - 1 < KT) load_stage((kt + GSTAGES - 1) % GSTAGES, kt + GSTAGES - 1);
        cp_commit();

        const uint32_t aS = aBase + cur * A_STAGE_BYTES;
        const uint32_t bS = bBase + cur * B_STAGE_BYTES;

#pragma unroll
        for (int ks = 0; ks < GBK / 16; ks++) {
            uint32_t af[4][4];
#pragma unroll
            for (int mi = 0; mi < 4; mi++) {
                int row = a_row + mi * 16;
                int col = ks * 16 + a_col8;
                uint32_t addr = aS + row * 128 + ((((col >> 3) ^ (row & 7)) & 7) << 4);
                ldsm4(af[mi], addr);
            }
            uint32_t bfr[4][2];
#pragma unroll
            for (int np = 0; np < 2; np++) {
                int row = ks * 16 + b_row;
                int col = b_colb + np * 16;
                int ch = (col >> 3);
                ch = (ch & 8) | ((ch ^ (row & 7)) & 7);
                uint32_t addr = bS + row * 256 + (ch << 4);
                uint32_t tmp[4];
                ldsm4t(tmp, addr);
                bfr[np * 2][0] = tmp[0]; bfr[np * 2][1] = tmp[1];
                bfr[np * 2 + 1][0] = tmp[2]; bfr[np * 2 + 1][1] = tmp[3];
            }
#pragma unroll
            for (int mi = 0; mi < 4; mi++)
#pragma unroll
                for (int ni = 0; ni < 4; ni++)
                    mma_f16(acc[mi][ni], af[mi], bfr[ni]);
        }

        asm volatile("cp.async.wait_group %0;\n" :: "n"(GSTAGES - 2));
        __syncthreads();
    }

#pragma unroll
    for (int mi = 0; mi < 4; mi++) {
#pragma unroll
        for (int ni = 0; ni < 4; ni++) {
            int row = bm * GBM + wm * 64 + mi * 16 + (lane >> 2);
            int col = bn * GBN + wn * 32 + ni * 8 + (lane & 3) * 2;
            if constexpr (sizeof(OutT) == 4) {
                float* Cp = (float*)C;
                *(float2*)&Cp[(size_t)row * N + col] = make_float2(acc[mi][ni][0], acc[mi][ni][1]);
                *(float2*)&Cp[(size_t)(row + 8) * N + col] = make_float2(acc[mi][ni][2], acc[mi][ni][3]);
            } else {
                __half* Cp = (__half*)C;
                *(uint32_t*)&Cp[(size_t)row * N + col] = packh2(acc[mi][ni][0], acc[mi][ni][1]);
                *(uint32_t*)&Cp[(size_t)(row + 8) * N + col] = packh2(acc[mi][ni][2], acc[mi][ni][3]);
            }
        }
    }
}

// ---------------------------------------------------------------------------
// RoPE -> fp16 (reads fp16 qkv at head offset hoff; scale folded) — simple form
// ---------------------------------------------------------------------------
__global__ void rope_f16(const __half* __restrict__ x, int hoff,
                         const float* __restrict__ cosp, const float* __restrict__ sinp,
                         __half* __restrict__ o, int nheads, float scale) {
    int idx = blockIdx.x * blockDim.x + threadIdx.x;
    int total = B_ * T_ * nheads * 64;
    if (idx >= total) return;
    int d = idx & 63;
    int h = (idx >> 6) % nheads;
    int tok = idx / (64 * nheads);
    int t = tok & (T_ - 1);
    size_t ib = (size_t)tok * NQKV + hoff + h * HD_;
    size_t ob = ((size_t)tok * nheads + h) * HD_;
    float c1 = cosp[t * HD_ + d], s1 = sinp[t * HD_ + d];
    float c2 = cosp[t * HD_ + d + 64], s2 = sinp[t * HD_ + d + 64];
    float x1 = __half2float(x[ib + d]), x2 = __half2float(x[ib + d + 64]);
    o[ob + d] = __float2half((x1 * c1 - x2 * s1) * scale);
    o[ob + d + 64] = __float2half((x2 * c2 + x1 * s2) * scale);
}

// V slice of fp16 qkv (cols 2560..3071) -> dense fp16 (vectorized 8-wide)
__global__ void cvt_v_f16(const __half* __restrict__ in, __half* __restrict__ o, int total8) {
    int i = blockIdx.x * blockDim.x + threadIdx.x;
    if (i >= total8) return;
    int tok = i >> 6, r8 = (i & 63) << 3;
    *(uint4*)(o + (size_t)i * 8) = *(const uint4*)(in + (size_t)tok * NQKV + 2560 + r8);
}

// ---------------------------------------------------------------------------
// fp16 flash attention (R10 engine + largest-qtile-first ordering).
// BM=BN=64, 128 threads, 48 KB smem, 4 CTAs/SM.
// ---------------------------------------------------------------------------
#define FTILE (64 * 128 * 2)

__global__ __launch_bounds__(128) void flash_f16(const __half* __restrict__ Qf,
                                                 const __half* __restrict__ Kf,
                                                 const __half* __restrict__ Vf,
                                                 __half* __restrict__ ctxH) {
    extern __shared__ char sm[];
    const uint32_t smBase = (uint32_t)__cvta_generic_to_shared(sm);
    const uint32_t sQ = smBase;
    const uint32_t sK = smBase + FTILE;
    const uint32_t sV = smBase + 2 * FTILE;

    const int tid = threadIdx.x;
    const int warp = tid >> 5, lane = tid & 31;
    const int qtile = (T_ / 64 - 1) - blockIdx.x;   // heavy CTAs first
    const int h = blockIdx.y;
    const int b = blockIdx.z;
    const int kvh = h / (NH_ / KVH_);
    const int q0 = qtile * 64;

    auto loadTile = [&](uint32_t sbase, const __half* g, size_t gbase, int gstride) {
#pragma unroll
        for (int i = 0; i < 8; i++) {
            int q = tid + i * 128;
            int r = q >> 4, c = q & 15;
            int ch = (c & 8) | ((c ^ (r & 7)) & 7);
            cp16(sbase + r * 256 + (ch << 4), g + gbase + (size_t)r * gstride + c * 8);
        }
    };

    const size_t qgb = ((size_t)(b * T_ + q0) * NH_ + h) * HD_;
    loadTile(sQ, Qf, qgb, NH_ * HD_);
    cp_commit();

    float oAcc[16][4];
#pragma unroll
    for (int j = 0; j < 16; j++)
#pragma unroll
        for (int e = 0; e < 4; e++) oAcc[j][e] = 0.f;
    float mrow[2] = {-1e30f, -1e30f};
    float lrow[2] = {0.f, 0.f};

    for (int t0 = 0; t0 <= qtile; t0++) {
        const int s0 = t0 * 64;
        __syncthreads();
        const size_t kgb = ((size_t)(b * T_ + s0) * KVH_ + kvh) * HD_;
        loadTile(sK, Kf, kgb, KVH_ * HD_);
        loadTile(sV, Vf, kgb, KVH_ * HD_);
        cp_commit();
        asm volatile("cp.async.wait_group 0;\n" ::);
        __syncthreads();

        // ---- S = Q K^T ----
        float sAcc[8][4];
#pragma unroll
        for (int j = 0; j < 8; j++)
#pragma unroll
            for (int e = 0; e < 4; e++) sAcc[j][e] = 0.f;

#pragma unroll
        for (int ks = 0; ks < 8; ks++) {
            int arow = warp * 16 + (lane & 15);
            int ac = ks * 2 + (lane >> 4);
            int ach = (ac & 8) | ((ac ^ (arow & 7)) & 7);
            uint32_t a4[4];
            ldsm4(a4, sQ + arow * 256 + (ach << 4));
            int krow_base = (lane & 7) + ((lane >> 4) & 1) * 8;
            int kc = ks * 2 + ((lane >> 3) & 1);
#pragma unroll
            for (int jp = 0; jp < 4; jp++) {
                int krow = jp * 16 + krow_base;
                int kch = (kc & 8) | ((kc ^ (krow & 7)) & 7);
                uint32_t b4[4];
                ldsm4(b4, sK + krow * 256 + (kch << 4));
                mma_f16(sAcc[jp * 2], a4, b4);
                mma_f16(sAcc[jp * 2 + 1], a4, &b4[2]);
            }
        }

        if (t0 == qtile) {
            int r0 = warp * 16 + (lane >> 2);
#pragma unroll
            for (int j = 0; j < 8; j++) {
                int cb = j * 8 + (lane & 3) * 2;
                if (cb > r0) sAcc[j][0] = -1e30f;
                if (cb + 1 > r0) sAcc[j][1] = -1e30f;
                if (cb > r0 + 8) sAcc[j][2] = -1e30f;
                if (cb + 1 > r0 + 8) sAcc[j][3] = -1e30f;
            }
        }

        // ---- online softmax ----
        float mx0 = -1e30f, mx1 = -1e30f;
#pragma unroll
        for (int j = 0; j < 8; j++) {
            mx0 = fmaxf(mx0, fmaxf(sAcc[j][0], sAcc[j][1]));
            mx1 = fmaxf(mx1, fmaxf(sAcc[j][2], sAcc[j][3]));
        }
        mx0 = fmaxf(mx0, __shfl_xor_sync(0xffffffffu, mx0, 1));
        mx0 = fmaxf(mx0, __shfl_xor_sync(0xffffffffu, mx0, 2));
        mx1 = fmaxf(mx1, __shfl_xor_sync(0xffffffffu, mx1, 1));
        mx1 = fmaxf(mx1, __shfl_xor_sync(0xffffffffu, mx1, 2));
        float mn0 = fmaxf(mrow[0], mx0);
        float mn1 = fmaxf(mrow[1], mx1);
        float al0 = ex2(mrow[0] - mn0);
        float al1 = ex2(mrow[1] - mn1);
        mrow[0] = mn0;
        mrow[1] = mn1;
        float sum0 = 0.f, sum1 = 0.f;
#pragma unroll
        for (int j = 0; j < 8; j++) {
            sAcc[j][0] = ex2(sAcc[j][0] - mn0);
            sAcc[j][1] = ex2(sAcc[j][1] - mn0);
            sAcc[j][2] = ex2(sAcc[j][2] - mn1);
            sAcc[j][3] = ex2(sAcc[j][3] - mn1);
            sum0 += sAcc[j][0] + sAcc[j][1];
            sum1 += sAcc[j][2] + sAcc[j][3];
        }
        sum0 += __shfl_xor_sync(0xffffffffu, sum0, 1);
        sum0 += __shfl_xor_sync(0xffffffffu, sum0, 2);
        sum1 += __shfl_xor_sync(0xffffffffu, sum1, 1);
        sum1 += __shfl_xor_sync(0xffffffffu, sum1, 2);
        lrow[0] = lrow[0] * al0 + sum0;
        lrow[1] = lrow[1] * al1 + sum1;
#pragma unroll
        for (int j = 0; j < 16; j++) {
            oAcc[j][0] *= al0;
            oAcc[j][1] *= al0;
            oAcc[j][2] *= al1;
            oAcc[j][3] *= al1;
        }

        // ---- O += P V ----
        int vrow_b = (lane & 15);
        int vcb = (lane >> 4);
#pragma unroll
        for (int kt = 0; kt < 4; kt++) {
            uint32_t pf[4];
            pf[0] = packh2(sAcc[2 * kt][0], sAcc[2 * kt][1]);
            pf[1] = packh2(sAcc[2 * kt][2], sAcc[2 * kt][3]);
            pf[2] = packh2(sAcc[2 * kt + 1][0], sAcc[2 * kt + 1][1]);
            pf[3] = packh2(sAcc[2 * kt + 1][2], sAcc[2 * kt + 1][3]);
            int vrow = kt * 16 + vrow_b;
#pragma unroll
            for (int jp2 = 0; jp2 < 8; jp2++) {
                int vc = jp2 * 2 + vcb;
                int vch = (vc & 8) | ((vc ^ (vrow & 7)) & 7);
                uint32_t v4[4];
                ldsm4t(v4, sV + vrow * 256 + (vch << 4));
                mma_f16(oAcc[jp2 * 2], pf, v4);
                mma_f16(oAcc[jp2 * 2 + 1], pf, &v4[2]);
            }
        }
    }

    // epilogue: normalize, write fp16 ctx (b,t,h,d)
    float inv0 = 1.f / lrow[0];
    float inv1 = 1.f / lrow[1];
    int r0 = q0 + warp * 16 + (lane >> 2);
    size_t row0 = (size_t)(b * T_ + r0) * HID_;
    size_t row1 = row0 + (size_t)8 * HID_;
#pragma unroll
    for (int j = 0; j < 16; j++) {
        int col = h * HD_ + j * 8 + (lane & 3) * 2;
        *(uint32_t*)(ctxH + row0 + col) = packh2(oAcc[j][0] * inv0, oAcc[j][1] * inv0);
        *(uint32_t*)(ctxH + row1 + col) = packh2(oAcc[j][2] * inv1, oAcc[j][3] * inv1);
    }
}

// ---------------------------------------------------------------------------
// Launch
// ---------------------------------------------------------------------------
extern "C" void kernel_launch(void* const* d_in, const int* in_sizes, int n_in,
                              void* d_out, int out_size) {
    const float* hidden = (const float*)d_in[0];
    const float* cosp = (const float*)d_in[2];
    const float* sinp = (const float*)d_in[3];
    const float* Wq = (const float*)d_in[4];
    const float* Wk = (const float*)d_in[5];
    const float* Wv = (const float*)d_in[6];
    const float* Wo = (const float*)d_in[7];
    float* out = (float*)d_out;

    __half *qkv, *hid_h, *wqkv_h, *wo_h, *ctx_h, *qf, *kf, *vf;
    cudaGetSymbolAddress((void**)&qkv, g_qkv);
    cudaGetSymbolAddress((void**)&hid_h, g_hid_h);
    cudaGetSymbolAddress((void**)&wqkv_h, g_wqkv_h);
    cudaGetSymbolAddress((void**)&wo_h, g_wo_h);
    cudaGetSymbolAddress((void**)&ctx_h, g_ctx_h);
    cudaGetSymbolAddress((void**)&qf, g_qf);
    cudaGetSymbolAddress((void**)&kf, g_kf);
    cudaGetSymbolAddress((void**)&vf, g_vf);

    const int M = B_ * T_;  // 4096

    constexpr int GEMM_SMEM = GSTAGES * (A_STAGE_BYTES + B_STAGE_BYTES);  // 96 KB
    cudaFuncSetAttribute(f16gemm<__half>, cudaFuncAttributeMaxDynamicSharedMemorySize, GEMM_SMEM);
    cudaFuncSetAttribute(f16gemm<float>, cudaFuncAttributeMaxDynamicSharedMemorySize, GEMM_SMEM);
    cudaFuncSetAttribute(flash_f16, cudaFuncAttributeMaxDynamicSharedMemorySize, 3 * FTILE);

    // converts (2 launches)
    cvt_f16<<<(M * KDIM / 8 + 255) / 256, 256>>>(hidden, hid_h, M * KDIM / 8);
    cvt_weights<<<(WQ_E + WK_E + WV_E + WO_E + 255) / 256, 256>>>(Wq, Wk, Wv, Wo, wqkv_h, wo_h);

    // fused QKV projection -> fp16
    f16gemm<__half><<<dim3(NQKV / GBN, M / GBM), 256, GEMM_SMEM>>>(hid_h, wqkv_h, qkv, M, NQKV, KDIM);

    // RoPE + V copy (simple dense kernels, fp16 input)
    const float qscale = 1.4426950408889634f * 0.08838834764831845f;
    rope_f16<<<(B_ * T_ * NH_ * 64 + 255) / 256, 256>>>(qkv, 0, cosp, sinp, qf, NH_, qscale);
    rope_f16<<<(B_ * T_ * KVH_ * 64 + 255) / 256, 256>>>(qkv, 2048, cosp, sinp, kf, KVH_, 1.0f);
    cvt_v_f16<<<(M * 512 / 8 + 255) / 256, 256>>>(qkv, vf, M * 512 / 8);

    // flash attention (dense V) -> fp16 ctx
    flash_f16<<<dim3(T_ / 64, NH_, B_), 128, 3 * FTILE>>>(qf, kf, vf, ctx_h);

    // output projection -> fp32
    f16gemm<float><<<dim3(2048 / GBN, M / GBM), 256, GEMM_SMEM>>>(ctx_h, wo_h, out, M, 2048, KDIM);
}

// round 13
// speedup vs baseline: 1.0543x; 1.0063x over previous
#include <cuda_runtime.h>
#include <cuda_fp16.h>
#include <cstdint>

#define B_ 2
#define T_ 2048
#define HID_ 2048
#define NH_ 16
#define KVH_ 4
#define HD_ 128
#define NQKV 3072
#define KDIM 2048

// fp16 QKV GEMM output (Q | K | V per token row)
__device__ __half g_qkv[(size_t)B_ * T_ * NQKV];
// fp16 GEMM operands
__device__ __half g_hid_h[(size_t)4096 * KDIM];
__device__ __half g_wqkv_h[(size_t)KDIM * NQKV];
__device__ __half g_wo_h[(size_t)KDIM * HID_];
__device__ __half g_ctx_h[(size_t)4096 * HID_];   // written by flash epilogue
// fp16 flash inputs (dense; Q is roped in-flash)
__device__ __half g_kf[(size_t)B_ * T_ * KVH_ * HD_];
__device__ __half g_vf[(size_t)B_ * T_ * KVH_ * HD_];

// ---------------------------------------------------------------------------
// helpers
// ---------------------------------------------------------------------------
__device__ __forceinline__ void cp16(uint32_t s, const void* g) {
    asm volatile("cp.async.cg.shared.global [%0], [%1], 16;\n" :: "r"(s), "l"(g));
}
__device__ __forceinline__ void cp_commit() {
    asm volatile("cp.async.commit_group;\n" ::);
}
__device__ __forceinline__ void mma_f16(float* c, const uint32_t* a, const uint32_t* b) {
    asm volatile(
        "mma.sync.aligned.m16n8k16.row.col.f32.f16.f16.f32 "
        "{%0,%1,%2,%3}, {%4,%5,%6,%7}, {%8,%9}, {%0,%1,%2,%3};\n"
        : "+f"(c[0]), "+f"(c[1]), "+f"(c[2]), "+f"(c[3])
        : "r"(a[0]), "r"(a[1]), "r"(a[2]), "r"(a[3]), "r"(b[0]), "r"(b[1]));
}
__device__ __forceinline__ void ldsm4(uint32_t* d, uint32_t addr) {
    asm volatile("ldmatrix.sync.aligned.m8n8.x4.shared.b16 {%0,%1,%2,%3}, [%4];\n"
                 : "=r"(d[0]), "=r"(d[1]), "=r"(d[2]), "=r"(d[3]) : "r"(addr));
}
__device__ __forceinline__ void ldsm4t(uint32_t* d, uint32_t addr) {
    asm volatile("ldmatrix.sync.aligned.m8n8.x4.trans.shared.b16 {%0,%1,%2,%3}, [%4];\n"
                 : "=r"(d[0]), "=r"(d[1]), "=r"(d[2]), "=r"(d[3]) : "r"(addr));
}
__device__ __forceinline__ float ex2(float x) {
    float r;
    asm("ex2.approx.f32 %0, %1;" : "=f"(r) : "f"(x));
    return r;
}
__device__ __forceinline__ uint32_t packh2(float a, float b) {
    __half2 t = __floats2half2_rn(a, b);
    return *(uint32_t*)&t;
}

// ---------------------------------------------------------------------------
// converts
// ---------------------------------------------------------------------------
__global__ void cvt_f16(const float* __restrict__ in, __half* __restrict__ out,
                        int total8) {
    int i = blockIdx.x * blockDim.x + threadIdx.x;
    if (i >= total8) return;
    float4 x0 = *(const float4*)(in + (size_t)i * 8);
    float4 x1 = *(const float4*)(in + (size_t)i * 8 + 4);
    __half2 h[4];
    h[0] = __floats2half2_rn(x0.x, x0.y);
    h[1] = __floats2half2_rn(x0.z, x0.w);
    h[2] = __floats2half2_rn(x1.x, x1.y);
    h[3] = __floats2half2_rn(x1.z, x1.w);
    *(uint4*)(out + (size_t)i * 8) = *(uint4*)h;
}

// all 4 weight matrices in one launch
#define WQ_E (KDIM * 2048)
#define WK_E (KDIM * 512)
#define WV_E (KDIM * 512)
#define WO_E (KDIM * 2048)
__global__ void cvt_weights(const float* __restrict__ Wq, const float* __restrict__ Wk,
                            const float* __restrict__ Wv, const float* __restrict__ Wo,
                            __half* __restrict__ wqkv, __half* __restrict__ wo) {
    int i = blockIdx.x * blockDim.x + threadIdx.x;
    if (i < WQ_E) {
        int k = i >> 11, n = i & 2047;
        wqkv[(size_t)k * NQKV + n] = __float2half(Wq[i]);
        return;
    }
    i -= WQ_E;
    if (i < WK_E) {
        int k = i >> 9, n = i & 511;
        wqkv[(size_t)k * NQKV + 2048 + n] = __float2half(Wk[i]);
        return;
    }
    i -= WK_E;
    if (i < WV_E) {
        int k = i >> 9, n = i & 511;
        wqkv[(size_t)k * NQKV + 2560 + n] = __float2half(Wv[i]);
        return;
    }
    i -= WV_E;
    if (i < WO_E) {
        int k = i >> 11, n = i & 2047;
        wo[(size_t)k * 2048 + n] = __float2half(Wo[i]);
    }
}

// ---------------------------------------------------------------------------
// fp16 GEMM, templated output type
// ---------------------------------------------------------------------------
#define GBM 128
#define GBN 128
#define GBK 64
#define GSTAGES 3
#define A_STAGE_BYTES (GBM * GBK * 2)
#define B_STAGE_BYTES (GBK * GBN * 2)

template <typename OutT>
__global__ __launch_bounds__(256) void f16gemm(const __half* __restrict__ A,
                                               const __half* __restrict__ B,
                                               OutT* __restrict__ C,
                                               int M, int N, int K) {
    extern __shared__ char sm[];
    const uint32_t smBase = (uint32_t)__cvta_generic_to_shared(sm);
    const uint32_t aBase = smBase;
    const uint32_t bBase = smBase + GSTAGES * A_STAGE_BYTES;

    const int tid = threadIdx.x;
    const int bm = blockIdx.y, bn = blockIdx.x;
    const int warp = tid >> 5, lane = tid & 31;
    const int wm = warp >> 2;
    const int wn = warp & 3;

    float acc[4][4][4];
#pragma unroll
    for (int mi = 0; mi < 4; mi++)
#pragma unroll
        for (int ni = 0; ni < 4; ni++)
#pragma unroll
            for (int e = 0; e < 4; e++) acc[mi][ni][e] = 0.f;

    const int KT = K / GBK;

    auto load_stage = [&](int sidx, int kt) {
#pragma unroll
        for (int i = 0; i < 4; i++) {
            int q = tid + i * 256;
            int r = q >> 3, c = q & 7;
            const __half* g = A + (size_t)(bm * GBM + r) * K + kt * GBK + c * 8;
            uint32_t s = aBase + sidx * A_STAGE_BYTES + r * 128 + (((c ^ (r & 7)) & 7) << 4);
            cp16(s, g);
        }
#pragma unroll
        for (int i = 0; i < 4; i++) {
            int q = tid + i * 256;
            int r = q >> 4, c = q & 15;
            const __half* g = B + (size_t)(kt * GBK + r) * N + bn * GBN + c * 8;
            int ch = (c & 8) | ((c ^ (r & 7)) & 7);
            uint32_t s = bBase + sidx * B_STAGE_BYTES + r * 256 + (ch << 4);
            cp16(s, g);
        }
    };

#pragma unroll
    for (int s = 0; s < GSTAGES - 1; s++) {
        load_stage(s, s);
        cp_commit();
    }
    asm volatile("cp.async.wait_group %0;\n" :: "n"(GSTAGES - 2));
    __syncthreads();

    const int a_row = wm * 64 + (lane & 15);
    const int a_col8 = (lane >> 4) * 8;
    const int b_row = (lane & 15);
    const int b_colb = wn * 32 + (lane >> 4) * 8;

    for (int kt = 0; kt < KT; kt++) {
        const int cur = kt % GSTAGES;
        if (kt + GSTAGES - 1 < KT) load_stage((kt + GSTAGES - 1) % GSTAGES, kt + GSTAGES - 1);
        cp_commit();

        const uint32_t aS = aBase + cur * A_STAGE_BYTES;
        const uint32_t bS = bBase + cur * B_STAGE_BYTES;

#pragma unroll
        for (int ks = 0; ks < GBK / 16; ks++) {
            uint32_t af[4][4];
#pragma unroll
            for (int mi = 0; mi < 4; mi++) {
                int row = a_row + mi * 16;
                int col = ks * 16 + a_col8;
                uint32_t addr = aS + row * 128 + ((((col >> 3) ^ (row & 7)) & 7) << 4);
                ldsm4(af[mi], addr);
            }
            uint32_t bfr[4][2];
#pragma unroll
            for (int np = 0; np < 2; np++) {
                int row = ks * 16 + b_row;
                int col = b_colb + np * 16;
                int ch = (col >> 3);
                ch = (ch & 8) | ((ch ^ (row & 7)) & 7);
                uint32_t addr = bS + row * 256 + (ch << 4);
                uint32_t tmp[4];
                ldsm4t(tmp, addr);
                bfr[np * 2][0] = tmp[0]; bfr[np * 2][1] = tmp[1];
                bfr[np * 2 + 1][0] = tmp[2]; bfr[np * 2 + 1][1] = tmp[3];
            }
#pragma unroll
            for (int mi = 0; mi < 4; mi++)
#pragma unroll
                for (int ni = 0; ni < 4; ni++)
                    mma_f16(acc[mi][ni], af[mi], bfr[ni]);
        }

        asm volatile("cp.async.wait_group %0;\n" :: "n"(GSTAGES - 2));
        __syncthreads();
    }

#pragma unroll
    for (int mi = 0; mi < 4; mi++) {
#pragma unroll
        for (int ni = 0; ni < 4; ni++) {
            int row = bm * GBM + wm * 64 + mi * 16 + (lane >> 2);
            int col = bn * GBN + wn * 32 + ni * 8 + (lane & 3) * 2;
            if constexpr (sizeof(OutT) == 4) {
                float* Cp = (float*)C;
                *(float2*)&Cp[(size_t)row * N + col] = make_float2(acc[mi][ni][0], acc[mi][ni][1]);
                *(float2*)&Cp[(size_t)(row + 8) * N + col] = make_float2(acc[mi][ni][2], acc[mi][ni][3]);
            } else {
                __half* Cp = (__half*)C;
                *(uint32_t*)&Cp[(size_t)row * N + col] = packh2(acc[mi][ni][0], acc[mi][ni][1]);
                *(uint32_t*)&Cp[(size_t)(row + 8) * N + col] = packh2(acc[mi][ni][2], acc[mi][ni][3]);
            }
        }
    }
}

// ---------------------------------------------------------------------------
// Vectorized K RoPE: 8 rotation pairs per thread (uint4 I/O).
// ---------------------------------------------------------------------------
__global__ void rope_k_vec(const __half* __restrict__ qkv,
                           const float* __restrict__ cosp, const float* __restrict__ sinp,
                           __half* __restrict__ kf) {
    int idx = blockIdx.x * blockDim.x + threadIdx.x;
    int total = B_ * T_ * KVH_ * 8;   // tasks of 8 pairs
    if (idx >= total) return;
    int c = idx & 7;
    int h = (idx >> 3) & (KVH_ - 1);
    int tok = idx >> 5;
    int t = tok & (T_ - 1);
    int d0 = c * 8;
    const __half* src = qkv + (size_t)tok * NQKV + 2048 + h * HD_;
    __half* dst = kf + ((size_t)tok * KVH_ + h) * HD_;
    __half xl[8], xh[8], yl[8], yh[8];
    *(uint4*)xl = *(const uint4*)(src + d0);
    *(uint4*)xh = *(const uint4*)(src + d0 + 64);
#pragma unroll
    for (int j = 0; j < 8; j++) {
        int d = d0 + j;
        float c1 = cosp[t * HD_ + d], s1 = sinp[t * HD_ + d];
        float c2 = cosp[t * HD_ + d + 64], s2 = sinp[t * HD_ + d + 64];
        float x1 = __half2float(xl[j]), x2 = __half2float(xh[j]);
        yl[j] = __float2half(x1 * c1 - x2 * s1);
        yh[j] = __float2half(x2 * c2 + x1 * s2);
    }
    *(uint4*)(dst + d0) = *(uint4*)yl;
    *(uint4*)(dst + d0 + 64) = *(uint4*)yh;
}

// V slice of fp16 qkv (cols 2560..3071) -> dense fp16 (vectorized 8-wide)
__global__ void cvt_v_f16(const __half* __restrict__ in, __half* __restrict__ o, int total8) {
    int i = blockIdx.x * blockDim.x + threadIdx.x;
    if (i >= total8) return;
    int tok = i >> 6, r8 = (i & 63) << 3;
    *(uint4*)(o + (size_t)i * 8) = *(const uint4*)(in + (size_t)tok * NQKV + 2560 + r8);
}

// ---------------------------------------------------------------------------
// fp16 flash attention with fused Q-RoPE prologue.
// BM=BN=64, 128 threads, 48 KB smem, 4 CTAs/SM, heavy qtiles first.
// ---------------------------------------------------------------------------
#define FTILE (64 * 128 * 2)

__global__ __launch_bounds__(128) void flash_f16(const __half* __restrict__ qkv,
                                                 const __half* __restrict__ Kf,
                                                 const __half* __restrict__ Vf,
                                                 const float* __restrict__ cosp,
                                                 const float* __restrict__ sinp,
                                                 __half* __restrict__ ctxH,
                                                 float qscale) {
    extern __shared__ char sm[];
    const uint32_t smBase = (uint32_t)__cvta_generic_to_shared(sm);
    const uint32_t sQ = smBase;
    const uint32_t sK = smBase + FTILE;
    const uint32_t sV = smBase + 2 * FTILE;

    const int tid = threadIdx.x;
    const int warp = tid >> 5, lane = tid & 31;
    const int qtile = (T_ / 64 - 1) - blockIdx.x;   // heavy CTAs first
    const int h = blockIdx.y;
    const int b = blockIdx.z;
    const int kvh = h / (NH_ / KVH_);
    const int q0 = qtile * 64;

    auto loadTile = [&](uint32_t sbase, const __half* g, size_t gbase, int gstride) {
#pragma unroll
        for (int i = 0; i < 8; i++) {
            int q = tid + i * 128;
            int r = q >> 4, c = q & 15;
            int ch = (c & 8) | ((c ^ (r & 7)) & 7);
            cp16(sbase + r * 256 + (ch << 4), g + gbase + (size_t)r * gstride + c * 8);
        }
    };

    // ---- fused Q-RoPE prologue: qkv -> rotated, scaled, swizzled smem Q ----
    // 512 tasks: (row r in 0..63) x (chunk c in 0..7 covering d=c*8..c*8+7 and d+64)
#pragma unroll
    for (int i = 0; i < 4; i++) {
        int task = tid + i * 128;
        int r = task >> 3, c = task & 7;
        int t = q0 + r;
        const __half* src = qkv + (size_t)(b * T_ + t) * NQKV + h * HD_;
        int d0 = c * 8;
        __half xl[8], xh[8], yl[8], yh[8];
        *(uint4*)xl = *(const uint4*)(src + d0);
        *(uint4*)xh = *(const uint4*)(src + d0 + 64);
#pragma unroll
        for (int j = 0; j < 8; j++) {
            int d = d0 + j;
            float c1 = cosp[t * HD_ + d], s1 = sinp[t * HD_ + d];
            float c2 = cosp[t * HD_ + d + 64], s2 = sinp[t * HD_ + d + 64];
            float x1 = __half2float(xl[j]), x2 = __half2float(xh[j]);
            yl[j] = __float2half((x1 * c1 - x2 * s1) * qscale);
            yh[j] = __float2half((x2 * c2 + x1 * s2) * qscale);
        }
        int ch1 = (c ^ (r & 7)) & 7;      // lower-half chunk (bit3 = 0)
        int ch2 = ch1 | 8;                // upper-half chunk (bit3 = 1)
        *(uint4*)(sm + r * 256 + (ch1 << 4)) = *(uint4*)yl;
        *(uint4*)(sm + r * 256 + (ch2 << 4)) = *(uint4*)yh;
    }

    float oAcc[16][4];
#pragma unroll
    for (int j = 0; j < 16; j++)
#pragma unroll
        for (int e = 0; e < 4; e++) oAcc[j][e] = 0.f;
    float mrow[2] = {-1e30f, -1e30f};
    float lrow[2] = {0.f, 0.f};

    for (int t0 = 0; t0 <= qtile; t0++) {
        const int s0 = t0 * 64;
        __syncthreads();   // prev iter done with K/V; also publishes Q stores (iter 0)
        const size_t kgb = ((size_t)(b * T_ + s0) * KVH_ + kvh) * HD_;
        loadTile(sK, Kf, kgb, KVH_ * HD_);
        loadTile(sV, Vf, kgb, KVH_ * HD_);
        cp_commit();
        asm volatile("cp.async.wait_group 0;\n" ::);
        __syncthreads();

        // ---- S = Q K^T ----
        float sAcc[8][4];
#pragma unroll
        for (int j = 0; j < 8; j++)
#pragma unroll
            for (int e = 0; e < 4; e++) sAcc[j][e] = 0.f;

#pragma unroll
        for (int ks = 0; ks < 8; ks++) {
            int arow = warp * 16 + (lane & 15);
            int ac = ks * 2 + (lane >> 4);
            int ach = (ac & 8) | ((ac ^ (arow & 7)) & 7);
            uint32_t a4[4];
            ldsm4(a4, sQ + arow * 256 + (ach << 4));
            int krow_base = (lane & 7) + ((lane >> 4) & 1) * 8;
            int kc = ks * 2 + ((lane >> 3) & 1);
#pragma unroll
            for (int jp = 0; jp < 4; jp++) {
                int krow = jp * 16 + krow_base;
                int kch = (kc & 8) | ((kc ^ (krow & 7)) & 7);
                uint32_t b4[4];
                ldsm4(b4, sK + krow * 256 + (kch << 4));
                mma_f16(sAcc[jp * 2], a4, b4);
                mma_f16(sAcc[jp * 2 + 1], a4, &b4[2]);
            }
        }

        if (t0 == qtile) {
            int r0 = warp * 16 + (lane >> 2);
#pragma unroll
            for (int j = 0; j < 8; j++) {
                int cb = j * 8 + (lane & 3) * 2;
                if (cb > r0) sAcc[j][0] = -1e30f;
                if (cb + 1 > r0) sAcc[j][1] = -1e30f;
                if (cb > r0 + 8) sAcc[j][2] = -1e30f;
                if (cb + 1 > r0 + 8) sAcc[j][3] = -1e30f;
            }
        }

        // ---- online softmax ----
        float mx0 = -1e30f, mx1 = -1e30f;
#pragma unroll
        for (int j = 0; j < 8; j++) {
            mx0 = fmaxf(mx0, fmaxf(sAcc[j][0], sAcc[j][1]));
            mx1 = fmaxf(mx1, fmaxf(sAcc[j][2], sAcc[j][3]));
        }
        mx0 = fmaxf(mx0, __shfl_xor_sync(0xffffffffu, mx0, 1));
        mx0 = fmaxf(mx0, __shfl_xor_sync(0xffffffffu, mx0, 2));
        mx1 = fmaxf(mx1, __shfl_xor_sync(0xffffffffu, mx1, 1));
        mx1 = fmaxf(mx1, __shfl_xor_sync(0xffffffffu, mx1, 2));
        float mn0 = fmaxf(mrow[0], mx0);
        float mn1 = fmaxf(mrow[1], mx1);
        float al0 = ex2(mrow[0] - mn0);
        float al1 = ex2(mrow[1] - mn1);
        mrow[0] = mn0;
        mrow[1] = mn1;
        float sum0 = 0.f, sum1 = 0.f;
#pragma unroll
        for (int j = 0; j < 8; j++) {
            sAcc[j][0] = ex2(sAcc[j][0] - mn0);
            sAcc[j][1] = ex2(sAcc[j][1] - mn0);
            sAcc[j][2] = ex2(sAcc[j][2] - mn1);
            sAcc[j][3] = ex2(sAcc[j][3] - mn1);
            sum0 += sAcc[j][0] + sAcc[j][1];
            sum1 += sAcc[j][2] + sAcc[j][3];
        }
        sum0 += __shfl_xor_sync(0xffffffffu, sum0, 1);
        sum0 += __shfl_xor_sync(0xffffffffu, sum0, 2);
        sum1 += __shfl_xor_sync(0xffffffffu, sum1, 1);
        sum1 += __shfl_xor_sync(0xffffffffu, sum1, 2);
        lrow[0] = lrow[0] * al0 + sum0;
        lrow[1] = lrow[1] * al1 + sum1;
#pragma unroll
        for (int j = 0; j < 16; j++) {
            oAcc[j][0] *= al0;
            oAcc[j][1] *= al0;
            oAcc[j][2] *= al1;
            oAcc[j][3] *= al1;
        }

        // ---- O += P V ----
        int vrow_b = (lane & 15);
        int vcb = (lane >> 4);
#pragma unroll
        for (int kt = 0; kt < 4; kt++) {
            uint32_t pf[4];
            pf[0] = packh2(sAcc[2 * kt][0], sAcc[2 * kt][1]);
            pf[1] = packh2(sAcc[2 * kt][2], sAcc[2 * kt][3]);
            pf[2] = packh2(sAcc[2 * kt + 1][0], sAcc[2 * kt + 1][1]);
            pf[3] = packh2(sAcc[2 * kt + 1][2], sAcc[2 * kt + 1][3]);
            int vrow = kt * 16 + vrow_b;
#pragma unroll
            for (int jp2 = 0; jp2 < 8; jp2++) {
                int vc = jp2 * 2 + vcb;
                int vch = (vc & 8) | ((vc ^ (vrow & 7)) & 7);
                uint32_t v4[4];
                ldsm4t(v4, sV + vrow * 256 + (vch << 4));
                mma_f16(oAcc[jp2 * 2], pf, v4);
                mma_f16(oAcc[jp2 * 2 + 1], pf, &v4[2]);
            }
        }
    }

    // epilogue: normalize, write fp16 ctx (b,t,h,d)
    float inv0 = 1.f / lrow[0];
    float inv1 = 1.f / lrow[1];
    int r0 = q0 + warp * 16 + (lane >> 2);
    size_t row0 = (size_t)(b * T_ + r0) * HID_;
    size_t row1 = row0 + (size_t)8 * HID_;
#pragma unroll
    for (int j = 0; j < 16; j++) {
        int col = h * HD_ + j * 8 + (lane & 3) * 2;
        *(uint32_t*)(ctxH + row0 + col) = packh2(oAcc[j][0] * inv0, oAcc[j][1] * inv0);
        *(uint32_t*)(ctxH + row1 + col) = packh2(oAcc[j][2] * inv1, oAcc[j][3] * inv1);
    }
}

// ---------------------------------------------------------------------------
// Launch
// ---------------------------------------------------------------------------
extern "C" void kernel_launch(void* const* d_in, const int* in_sizes, int n_in,
                              void* d_out, int out_size) {
    const float* hidden = (const float*)d_in[0];
    const float* cosp = (const float*)d_in[2];
    const float* sinp = (const float*)d_in[3];
    const float* Wq = (const float*)d_in[4];
    const float* Wk = (const float*)d_in[5];
    const float* Wv = (const float*)d_in[6];
    const float* Wo = (const float*)d_in[7];
    float* out = (float*)d_out;

    __half *qkv, *hid_h, *wqkv_h, *wo_h, *ctx_h, *kf, *vf;
    cudaGetSymbolAddress((void**)&qkv, g_qkv);
    cudaGetSymbolAddress((void**)&hid_h, g_hid_h);
    cudaGetSymbolAddress((void**)&wqkv_h, g_wqkv_h);
    cudaGetSymbolAddress((void**)&wo_h, g_wo_h);
    cudaGetSymbolAddress((void**)&ctx_h, g_ctx_h);
    cudaGetSymbolAddress((void**)&kf, g_kf);
    cudaGetSymbolAddress((void**)&vf, g_vf);

    const int M = B_ * T_;  // 4096

    constexpr int GEMM_SMEM = GSTAGES * (A_STAGE_BYTES + B_STAGE_BYTES);  // 96 KB
    cudaFuncSetAttribute(f16gemm<__half>, cudaFuncAttributeMaxDynamicSharedMemorySize, GEMM_SMEM);
    cudaFuncSetAttribute(f16gemm<float>, cudaFuncAttributeMaxDynamicSharedMemorySize, GEMM_SMEM);
    cudaFuncSetAttribute(flash_f16, cudaFuncAttributeMaxDynamicSharedMemorySize, 3 * FTILE);

    // converts (2 launches)
    cvt_f16<<<(M * KDIM / 8 + 255) / 256, 256>>>(hidden, hid_h, M * KDIM / 8);
    cvt_weights<<<(WQ_E + WK_E + WV_E + WO_E + 255) / 256, 256>>>(Wq, Wk, Wv, Wo, wqkv_h, wo_h);

    // fused QKV projection -> fp16
    f16gemm<__half><<<dim3(NQKV / GBN, M / GBM), 256, GEMM_SMEM>>>(hid_h, wqkv_h, qkv, M, NQKV, KDIM);

    // K RoPE (vectorized) + V copy
    rope_k_vec<<<(B_ * T_ * KVH_ * 8 + 255) / 256, 256>>>(qkv, cosp, sinp, kf);
    cvt_v_f16<<<(M * 512 / 8 + 255) / 256, 256>>>(qkv, vf, M * 512 / 8);

    // flash attention with fused Q-RoPE -> fp16 ctx
    const float qscale = 1.4426950408889634f * 0.08838834764831845f;
    flash_f16<<<dim3(T_ / 64, NH_, B_), 128, 3 * FTILE>>>(qkv, kf, vf, cosp, sinp, ctx_h, qscale);

    // output projection -> fp32
    f16gemm<float><<<dim3(2048 / GBN, M / GBM), 256, GEMM_SMEM>>>(ctx_h, wo_h, out, M, 2048, KDIM);
}

// round 14
// speedup vs baseline: 1.0705x; 1.0154x over previous
#include <cuda_runtime.h>
#include <cuda_fp16.h>
#include <cstdint>

#define B_ 2
#define T_ 2048
#define HID_ 2048
#define NH_ 16
#define KVH_ 4
#define HD_ 128
#define NQKV 3072
#define KDIM 2048

// fp16 QKV GEMM output (Q | K | V per token row)
__device__ __half g_qkv[(size_t)B_ * T_ * NQKV];
// fp16 GEMM operands
__device__ __half g_hid_h[(size_t)4096 * KDIM];
__device__ __half g_wqkv_h[(size_t)KDIM * NQKV];
__device__ __half g_wo_h[(size_t)KDIM * HID_];
__device__ __half g_ctx_h[(size_t)4096 * HID_];   // written by flash epilogue
// fp16 flash inputs (dense; Q is roped in-flash)
__device__ __half g_kf[(size_t)B_ * T_ * KVH_ * HD_];
__device__ __half g_vf[(size_t)B_ * T_ * KVH_ * HD_];

// ---------------------------------------------------------------------------
// helpers
// ---------------------------------------------------------------------------
__device__ __forceinline__ void cp16(uint32_t s, const void* g) {
    asm volatile("cp.async.cg.shared.global [%0], [%1], 16;\n" :: "r"(s), "l"(g));
}
__device__ __forceinline__ void cp_commit() {
    asm volatile("cp.async.commit_group;\n" ::);
}
__device__ __forceinline__ void mma_f16(float* c, const uint32_t* a, const uint32_t* b) {
    asm volatile(
        "mma.sync.aligned.m16n8k16.row.col.f32.f16.f16.f32 "
        "{%0,%1,%2,%3}, {%4,%5,%6,%7}, {%8,%9}, {%0,%1,%2,%3};\n"
        : "+f"(c[0]), "+f"(c[1]), "+f"(c[2]), "+f"(c[3])
        : "r"(a[0]), "r"(a[1]), "r"(a[2]), "r"(a[3]), "r"(b[0]), "r"(b[1]));
}
__device__ __forceinline__ void ldsm4(uint32_t* d, uint32_t addr) {
    asm volatile("ldmatrix.sync.aligned.m8n8.x4.shared.b16 {%0,%1,%2,%3}, [%4];\n"
                 : "=r"(d[0]), "=r"(d[1]), "=r"(d[2]), "=r"(d[3]) : "r"(addr));
}
__device__ __forceinline__ void ldsm4t(uint32_t* d, uint32_t addr) {
    asm volatile("ldmatrix.sync.aligned.m8n8.x4.trans.shared.b16 {%0,%1,%2,%3}, [%4];\n"
                 : "=r"(d[0]), "=r"(d[1]), "=r"(d[2]), "=r"(d[3]) : "r"(addr));
}
__device__ __forceinline__ float ex2(float x) {
    float r;
    asm("ex2.approx.f32 %0, %1;" : "=f"(r) : "f"(x));
    return r;
}
__device__ __forceinline__ uint32_t packh2(float a, float b) {
    __half2 t = __floats2half2_rn(a, b);
    return *(uint32_t*)&t;
}

// ---------------------------------------------------------------------------
// converts
// ---------------------------------------------------------------------------
__global__ void cvt_f16(const float* __restrict__ in, __half* __restrict__ out,
                        int total8) {
    int i = blockIdx.x * blockDim.x + threadIdx.x;
    if (i >= total8) return;
    float4 x0 = *(const float4*)(in + (size_t)i * 8);
    float4 x1 = *(const float4*)(in + (size_t)i * 8 + 4);
    __half2 h[4];
    h[0] = __floats2half2_rn(x0.x, x0.y);
    h[1] = __floats2half2_rn(x0.z, x0.w);
    h[2] = __floats2half2_rn(x1.x, x1.y);
    h[3] = __floats2half2_rn(x1.z, x1.w);
    *(uint4*)(out + (size_t)i * 8) = *(uint4*)h;
}

// all 4 weight matrices in one launch
#define WQ_E (KDIM * 2048)
#define WK_E (KDIM * 512)
#define WV_E (KDIM * 512)
#define WO_E (KDIM * 2048)
__global__ void cvt_weights(const float* __restrict__ Wq, const float* __restrict__ Wk,
                            const float* __restrict__ Wv, const float* __restrict__ Wo,
                            __half* __restrict__ wqkv, __half* __restrict__ wo) {
    int i = blockIdx.x * blockDim.x + threadIdx.x;
    if (i < WQ_E) {
        int k = i >> 11, n = i & 2047;
        wqkv[(size_t)k * NQKV + n] = __float2half(Wq[i]);
        return;
    }
    i -= WQ_E;
    if (i < WK_E) {
        int k = i >> 9, n = i & 511;
        wqkv[(size_t)k * NQKV + 2048 + n] = __float2half(Wk[i]);
        return;
    }
    i -= WK_E;
    if (i < WV_E) {
        int k = i >> 9, n = i & 511;
        wqkv[(size_t)k * NQKV + 2560 + n] = __float2half(Wv[i]);
        return;
    }
    i -= WV_E;
    if (i < WO_E) {
        int k = i >> 11, n = i & 2047;
        wo[(size_t)k * 2048 + n] = __float2half(Wo[i]);
    }
}

// ---------------------------------------------------------------------------
// fp16 GEMM, templated output type (unchanged — at HMMA ceiling)
// ---------------------------------------------------------------------------
#define GBM 128
#define GBN 128
#define GBK 64
#define GSTAGES 3
#define A_STAGE_BYTES (GBM * GBK * 2)
#define B_STAGE_BYTES (GBK * GBN * 2)

template <typename OutT>
__global__ __launch_bounds__(256) void f16gemm(const __half* __restrict__ A,
                                               const __half* __restrict__ B,
                                               OutT* __restrict__ C,
                                               int M, int N, int K) {
    extern __shared__ char sm[];
    const uint32_t smBase = (uint32_t)__cvta_generic_to_shared(sm);
    const uint32_t aBase = smBase;
    const uint32_t bBase = smBase + GSTAGES * A_STAGE_BYTES;

    const int tid = threadIdx.x;
    const int bm = blockIdx.y, bn = blockIdx.x;
    const int warp = tid >> 5, lane = tid & 31;
    const int wm = warp >> 2;
    const int wn = warp & 3;

    float acc[4][4][4];
#pragma unroll
    for (int mi = 0; mi < 4; mi++)
#pragma unroll
        for (int ni = 0; ni < 4; ni++)
#pragma unroll
            for (int e = 0; e < 4; e++) acc[mi][ni][e] = 0.f;

    const int KT = K / GBK;

    auto load_stage = [&](int sidx, int kt) {
#pragma unroll
        for (int i = 0; i < 4; i++) {
            int q = tid + i * 256;
            int r = q >> 3, c = q & 7;
            const __half* g = A + (size_t)(bm * GBM + r) * K + kt * GBK + c * 8;
            uint32_t s = aBase + sidx * A_STAGE_BYTES + r * 128 + (((c ^ (r & 7)) & 7) << 4);
            cp16(s, g);
        }
#pragma unroll
        for (int i = 0; i < 4; i++) {
            int q = tid + i * 256;
            int r = q >> 4, c = q & 15;
            const __half* g = B + (size_t)(kt * GBK + r) * N + bn * GBN + c * 8;
            int ch = (c & 8) | ((c ^ (r & 7)) & 7);
            uint32_t s = bBase + sidx * B_STAGE_BYTES + r * 256 + (ch << 4);
            cp16(s, g);
        }
    };

#pragma unroll
    for (int s = 0; s < GSTAGES - 1; s++) {
        load_stage(s, s);
        cp_commit();
    }
    asm volatile("cp.async.wait_group %0;\n" :: "n"(GSTAGES - 2));
    __syncthreads();

    const int a_row = wm * 64 + (lane & 15);
    const int a_col8 = (lane >> 4) * 8;
    const int b_row = (lane & 15);
    const int b_colb = wn * 32 + (lane >> 4) * 8;

    for (int kt = 0; kt < KT; kt++) {
        const int cur = kt % GSTAGES;
        if (kt + GSTAGES - 1 < KT) load_stage((kt + GSTAGES - 1) % GSTAGES, kt + GSTAGES - 1);
        cp_commit();

        const uint32_t aS = aBase + cur * A_STAGE_BYTES;
        const uint32_t bS = bBase + cur * B_STAGE_BYTES;

#pragma unroll
        for (int ks = 0; ks < GBK / 16; ks++) {
            uint32_t af[4][4];
#pragma unroll
            for (int mi = 0; mi < 4; mi++) {
                int row = a_row + mi * 16;
                int col = ks * 16 + a_col8;
                uint32_t addr = aS + row * 128 + ((((col >> 3) ^ (row & 7)) & 7) << 4);
                ldsm4(af[mi], addr);
            }
            uint32_t bfr[4][2];
#pragma unroll
            for (int np = 0; np < 2; np++) {
                int row = ks * 16 + b_row;
                int col = b_colb + np * 16;
                int ch = (col >> 3);
                ch = (ch & 8) | ((ch ^ (row & 7)) & 7);
                uint32_t addr = bS + row * 256 + (ch << 4);
                uint32_t tmp[4];
                ldsm4t(tmp, addr);
                bfr[np * 2][0] = tmp[0]; bfr[np * 2][1] = tmp[1];
                bfr[np * 2 + 1][0] = tmp[2]; bfr[np * 2 + 1][1] = tmp[3];
            }
#pragma unroll
            for (int mi = 0; mi < 4; mi++)
#pragma unroll
                for (int ni = 0; ni < 4; ni++)
                    mma_f16(acc[mi][ni], af[mi], bfr[ni]);
        }

        asm volatile("cp.async.wait_group %0;\n" :: "n"(GSTAGES - 2));
        __syncthreads();
    }

#pragma unroll
    for (int mi = 0; mi < 4; mi++) {
#pragma unroll
        for (int ni = 0; ni < 4; ni++) {
            int row = bm * GBM + wm * 64 + mi * 16 + (lane >> 2);
            int col = bn * GBN + wn * 32 + ni * 8 + (lane & 3) * 2;
            if constexpr (sizeof(OutT) == 4) {
                float* Cp = (float*)C;
                *(float2*)&Cp[(size_t)row * N + col] = make_float2(acc[mi][ni][0], acc[mi][ni][1]);
                *(float2*)&Cp[(size_t)(row + 8) * N + col] = make_float2(acc[mi][ni][2], acc[mi][ni][3]);
            } else {
                __half* Cp = (__half*)C;
                *(uint32_t*)&Cp[(size_t)row * N + col] = packh2(acc[mi][ni][0], acc[mi][ni][1]);
                *(uint32_t*)&Cp[(size_t)(row + 8) * N + col] = packh2(acc[mi][ni][2], acc[mi][ni][3]);
            }
        }
    }
}

// ---------------------------------------------------------------------------
// Merged prep: K RoPE (blocks [0, KBLK)) + V copy (blocks [KBLK, KBLK+VBLK))
// ---------------------------------------------------------------------------
#define KTASKS (B_ * T_ * KVH_ * 8)       // 131072 -> 512 blocks
#define VTASKS (B_ * T_ * 512 / 8)        // 262144 -> 1024 blocks
#define KBLK (KTASKS / 256)
#define VBLK (VTASKS / 256)
__global__ void prep_kv(const __half* __restrict__ qkv,
                        const float* __restrict__ cosp, const float* __restrict__ sinp,
                        __half* __restrict__ kf, __half* __restrict__ vf) {
    if (blockIdx.x < KBLK) {
        int idx = blockIdx.x * 256 + threadIdx.x;
        int c = idx & 7;
        int h = (idx >> 3) & (KVH_ - 1);
        int tok = idx >> 5;
        int t = tok & (T_ - 1);
        int d0 = c * 8;
        const __half* src = qkv + (size_t)tok * NQKV + 2048 + h * HD_;
        __half* dst = kf + ((size_t)tok * KVH_ + h) * HD_;
        __half xl[8], xh[8], yl[8], yh[8];
        *(uint4*)xl = *(const uint4*)(src + d0);
        *(uint4*)xh = *(const uint4*)(src + d0 + 64);
#pragma unroll
        for (int j = 0; j < 8; j++) {
            int d = d0 + j;
            float c1 = cosp[t * HD_ + d], s1 = sinp[t * HD_ + d];
            float c2 = cosp[t * HD_ + d + 64], s2 = sinp[t * HD_ + d + 64];
            float x1 = __half2float(xl[j]), x2 = __half2float(xh[j]);
            yl[j] = __float2half(x1 * c1 - x2 * s1);
            yh[j] = __float2half(x2 * c2 + x1 * s2);
        }
        *(uint4*)(dst + d0) = *(uint4*)yl;
        *(uint4*)(dst + d0 + 64) = *(uint4*)yh;
    } else {
        int i = (blockIdx.x - KBLK) * 256 + threadIdx.x;
        int tok = i >> 6, r8 = (i & 63) << 3;
        *(uint4*)(vf + (size_t)i * 8) = *(const uint4*)(qkv + (size_t)tok * NQKV + 2560 + r8);
    }
}

// ---------------------------------------------------------------------------
// fp16 flash attention: fused Q-RoPE prologue + double-buffered K/V.
// smem: Q 16K + 2x(K 16K) + 2x(V 16K) = 80 KB -> 2 CTAs/SM.
// ---------------------------------------------------------------------------
#define FTILE (64 * 128 * 2)   // 16 KB

__global__ __launch_bounds__(128) void flash_f16(const __half* __restrict__ qkv,
                                                 const __half* __restrict__ Kf,
                                                 const __half* __restrict__ Vf,
                                                 const float* __restrict__ cosp,
                                                 const float* __restrict__ sinp,
                                                 __half* __restrict__ ctxH,
                                                 float qscale) {
    extern __shared__ char sm[];
    const uint32_t smBase = (uint32_t)__cvta_generic_to_shared(sm);
    const uint32_t sQ = smBase;
    // buffers: sK[buf], sV[buf]
    const uint32_t sK0 = smBase + FTILE;
    const uint32_t sV0 = smBase + 3 * FTILE;

    const int tid = threadIdx.x;
    const int warp = tid >> 5, lane = tid & 31;
    const int qtile = (T_ / 64 - 1) - blockIdx.x;   // heavy CTAs first
    const int h = blockIdx.y;
    const int b = blockIdx.z;
    const int kvh = h / (NH_ / KVH_);
    const int q0 = qtile * 64;

    auto loadKV = [&](int buf, int s0) {
        const size_t kgb = ((size_t)(b * T_ + s0) * KVH_ + kvh) * HD_;
        const uint32_t kb = sK0 + buf * FTILE;
        const uint32_t vb = sV0 + buf * FTILE;
#pragma unroll
        for (int i = 0; i < 8; i++) {
            int q = tid + i * 128;
            int r = q >> 4, c = q & 15;
            int ch = (c & 8) | ((c ^ (r & 7)) & 7);
            cp16(kb + r * 256 + (ch << 4), Kf + kgb + (size_t)r * (KVH_ * HD_) + c * 8);
            cp16(vb + r * 256 + (ch << 4), Vf + kgb + (size_t)r * (KVH_ * HD_) + c * 8);
        }
    };

    // ---- fused Q-RoPE prologue ----
#pragma unroll
    for (int i = 0; i < 4; i++) {
        int task = tid + i * 128;
        int r = task >> 3, c = task & 7;
        int t = q0 + r;
        const __half* src = qkv + (size_t)(b * T_ + t) * NQKV + h * HD_;
        int d0 = c * 8;
        __half xl[8], xh[8], yl[8], yh[8];
        *(uint4*)xl = *(const uint4*)(src + d0);
        *(uint4*)xh = *(const uint4*)(src + d0 + 64);
#pragma unroll
        for (int j = 0; j < 8; j++) {
            int d = d0 + j;
            float c1 = cosp[t * HD_ + d], s1 = sinp[t * HD_ + d];
            float c2 = cosp[t * HD_ + d + 64], s2 = sinp[t * HD_ + d + 64];
            float x1 = __half2float(xl[j]), x2 = __half2float(xh[j]);
            yl[j] = __float2half((x1 * c1 - x2 * s1) * qscale);
            yh[j] = __float2half((x2 * c2 + x1 * s2) * qscale);
        }
        int ch1 = (c ^ (r & 7)) & 7;
        int ch2 = ch1 | 8;
        *(uint4*)(sm + r * 256 + (ch1 << 4)) = *(uint4*)yl;
        *(uint4*)(sm + r * 256 + (ch2 << 4)) = *(uint4*)yh;
    }

    // prologue load: tile 0 into buffer 0
    loadKV(0, 0);
    cp_commit();

    float oAcc[16][4];
#pragma unroll
    for (int j = 0; j < 16; j++)
#pragma unroll
        for (int e = 0; e < 4; e++) oAcc[j][e] = 0.f;
    float mrow[2] = {-1e30f, -1e30f};
    float lrow[2] = {0.f, 0.f};

    for (int t0 = 0; t0 <= qtile; t0++) {
        const int buf = t0 & 1;
        __syncthreads();   // all warps done with buf^1 (prev-prev tile); Q published (iter 0)
        if (t0 + 1 <= qtile) loadKV(buf ^ 1, (t0 + 1) * 64);
        cp_commit();                 // always commit (empty group on last iter)
        asm volatile("cp.async.wait_group 1;\n" ::);   // tile t0 resident
        __syncthreads();

        const uint32_t sK = sK0 + buf * FTILE;
        const uint32_t sV = sV0 + buf * FTILE;

        // ---- S = Q K^T ----
        float sAcc[8][4];
#pragma unroll
        for (int j = 0; j < 8; j++)
#pragma unroll
            for (int e = 0; e < 4; e++) sAcc[j][e] = 0.f;

#pragma unroll
        for (int ks = 0; ks < 8; ks++) {
            int arow = warp * 16 + (lane & 15);
            int ac = ks * 2 + (lane >> 4);
            int ach = (ac & 8) | ((ac ^ (arow & 7)) & 7);
            uint32_t a4[4];
            ldsm4(a4, sQ + arow * 256 + (ach << 4));
            int krow_base = (lane & 7) + ((lane >> 4) & 1) * 8;
            int kc = ks * 2 + ((lane >> 3) & 1);
#pragma unroll
            for (int jp = 0; jp < 4; jp++) {
                int krow = jp * 16 + krow_base;
                int kch = (kc & 8) | ((kc ^ (krow & 7)) & 7);
                uint32_t b4[4];
                ldsm4(b4, sK + krow * 256 + (kch << 4));
                mma_f16(sAcc[jp * 2], a4, b4);
                mma_f16(sAcc[jp * 2 + 1], a4, &b4[2]);
            }
        }

        if (t0 == qtile) {
            int r0 = warp * 16 + (lane >> 2);
#pragma unroll
            for (int j = 0; j < 8; j++) {
                int cb = j * 8 + (lane & 3) * 2;
                if (cb > r0) sAcc[j][0] = -1e30f;
                if (cb + 1 > r0) sAcc[j][1] = -1e30f;
                if (cb > r0 + 8) sAcc[j][2] = -1e30f;
                if (cb + 1 > r0 + 8) sAcc[j][3] = -1e30f;
            }
        }

        // ---- online softmax ----
        float mx0 = -1e30f, mx1 = -1e30f;
#pragma unroll
        for (int j = 0; j < 8; j++) {
            mx0 = fmaxf(mx0, fmaxf(sAcc[j][0], sAcc[j][1]));
            mx1 = fmaxf(mx1, fmaxf(sAcc[j][2], sAcc[j][3]));
        }
        mx0 = fmaxf(mx0, __shfl_xor_sync(0xffffffffu, mx0, 1));
        mx0 = fmaxf(mx0, __shfl_xor_sync(0xffffffffu, mx0, 2));
        mx1 = fmaxf(mx1, __shfl_xor_sync(0xffffffffu, mx1, 1));
        mx1 = fmaxf(mx1, __shfl_xor_sync(0xffffffffu, mx1, 2));
        float mn0 = fmaxf(mrow[0], mx0);
        float mn1 = fmaxf(mrow[1], mx1);
        float al0 = ex2(mrow[0] - mn0);
        float al1 = ex2(mrow[1] - mn1);
        mrow[0] = mn0;
        mrow[1] = mn1;
        float sum0 = 0.f, sum1 = 0.f;
#pragma unroll
        for (int j = 0; j < 8; j++) {
            sAcc[j][0] = ex2(sAcc[j][0] - mn0);
            sAcc[j][1] = ex2(sAcc[j][1] - mn0);
            sAcc[j][2] = ex2(sAcc[j][2] - mn1);
            sAcc[j][3] = ex2(sAcc[j][3] - mn1);
            sum0 += sAcc[j][0] + sAcc[j][1];
            sum1 += sAcc[j][2] + sAcc[j][3];
        }
        sum0 += __shfl_xor_sync(0xffffffffu, sum0, 1);
        sum0 += __shfl_xor_sync(0xffffffffu, sum0, 2);
        sum1 += __shfl_xor_sync(0xffffffffu, sum1, 1);
        sum1 += __shfl_xor_sync(0xffffffffu, sum1, 2);
        lrow[0] = lrow[0] * al0 + sum0;
        lrow[1] = lrow[1] * al1 + sum1;
#pragma unroll
        for (int j = 0; j < 16; j++) {
            oAcc[j][0] *= al0;
            oAcc[j][1] *= al0;
            oAcc[j][2] *= al1;
            oAcc[j][3] *= al1;
        }

        // ---- O += P V ----
        int vrow_b = (lane & 15);
        int vcb = (lane >> 4);
#pragma unroll
        for (int kt = 0; kt < 4; kt++) {
            uint32_t pf[4];
            pf[0] = packh2(sAcc[2 * kt][0], sAcc[2 * kt][1]);
            pf[1] = packh2(sAcc[2 * kt][2], sAcc[2 * kt][3]);
            pf[2] = packh2(sAcc[2 * kt + 1][0], sAcc[2 * kt + 1][1]);
            pf[3] = packh2(sAcc[2 * kt + 1][2], sAcc[2 * kt + 1][3]);
            int vrow = kt * 16 + vrow_b;
#pragma unroll
            for (int jp2 = 0; jp2 < 8; jp2++) {
                int vc = jp2 * 2 + vcb;
                int vch = (vc & 8) | ((vc ^ (vrow & 7)) & 7);
                uint32_t v4[4];
                ldsm4t(v4, sV + vrow * 256 + (vch << 4));
                mma_f16(oAcc[jp2 * 2], pf, v4);
                mma_f16(oAcc[jp2 * 2 + 1], pf, &v4[2]);
            }
        }
    }

    // epilogue: normalize, write fp16 ctx (b,t,h,d)
    float inv0 = 1.f / lrow[0];
    float inv1 = 1.f / lrow[1];
    int r0 = q0 + warp * 16 + (lane >> 2);
    size_t row0 = (size_t)(b * T_ + r0) * HID_;
    size_t row1 = row0 + (size_t)8 * HID_;
#pragma unroll
    for (int j = 0; j < 16; j++) {
        int col = h * HD_ + j * 8 + (lane & 3) * 2;
        *(uint32_t*)(ctxH + row0 + col) = packh2(oAcc[j][0] * inv0, oAcc[j][1] * inv0);
        *(uint32_t*)(ctxH + row1 + col) = packh2(oAcc[j][2] * inv1, oAcc[j][3] * inv1);
    }
}

// ---------------------------------------------------------------------------
// Launch
// ---------------------------------------------------------------------------
extern "C" void kernel_launch(void* const* d_in, const int* in_sizes, int n_in,
                              void* d_out, int out_size) {
    const float* hidden = (const float*)d_in[0];
    const float* cosp = (const float*)d_in[2];
    const float* sinp = (const float*)d_in[3];
    const float* Wq = (const float*)d_in[4];
    const float* Wk = (const float*)d_in[5];
    const float* Wv = (const float*)d_in[6];
    const float* Wo = (const float*)d_in[7];
    float* out = (float*)d_out;

    __half *qkv, *hid_h, *wqkv_h, *wo_h, *ctx_h, *kf, *vf;
    cudaGetSymbolAddress((void**)&qkv, g_qkv);
    cudaGetSymbolAddress((void**)&hid_h, g_hid_h);
    cudaGetSymbolAddress((void**)&wqkv_h, g_wqkv_h);
    cudaGetSymbolAddress((void**)&wo_h, g_wo_h);
    cudaGetSymbolAddress((void**)&ctx_h, g_ctx_h);
    cudaGetSymbolAddress((void**)&kf, g_kf);
    cudaGetSymbolAddress((void**)&vf, g_vf);

    const int M = B_ * T_;  // 4096

    constexpr int GEMM_SMEM = GSTAGES * (A_STAGE_BYTES + B_STAGE_BYTES);  // 96 KB
    constexpr int FLASH_SMEM = 5 * FTILE;  // 80 KB
    cudaFuncSetAttribute(f16gemm<__half>, cudaFuncAttributeMaxDynamicSharedMemorySize, GEMM_SMEM);
    cudaFuncSetAttribute(f16gemm<float>, cudaFuncAttributeMaxDynamicSharedMemorySize, GEMM_SMEM);
    cudaFuncSetAttribute(flash_f16, cudaFuncAttributeMaxDynamicSharedMemorySize, FLASH_SMEM);

    // converts (2 launches)
    cvt_f16<<<(M * KDIM / 8 + 255) / 256, 256>>>(hidden, hid_h, M * KDIM / 8);
    cvt_weights<<<(WQ_E + WK_E + WV_E + WO_E + 255) / 256, 256>>>(Wq, Wk, Wv, Wo, wqkv_h, wo_h);

    // fused QKV projection -> fp16
    f16gemm<__half><<<dim3(NQKV / GBN, M / GBM), 256, GEMM_SMEM>>>(hid_h, wqkv_h, qkv, M, NQKV, KDIM);

    // merged K-RoPE + V copy (1 launch)
    prep_kv<<<KBLK + VBLK, 256>>>(qkv, cosp, sinp, kf, vf);

    // flash attention (fused Q-RoPE, double-buffered K/V) -> fp16 ctx
    const float qscale = 1.4426950408889634f * 0.08838834764831845f;
    flash_f16<<<dim3(T_ / 64, NH_, B_), 128, FLASH_SMEM>>>(qkv, kf, vf, cosp, sinp, ctx_h, qscale);

    // output projection -> fp32
    f16gemm<float><<<dim3(2048 / GBN, M / GBM), 256, GEMM_SMEM>>>(ctx_h, wo_h, out, M, 2048, KDIM);
}